// round 4
// baseline (speedup 1.0000x reference)
#include <cuda_runtime.h>
#include <cuda_bf16.h>
#include <cstdint>

// ============================================================
// out[4096,4096] = x[4096,4096] @ W^T[4096,4096] + b
// bf16 split-3 (hi*hi + hi*lo + lo*hi) via mma.sync HMMA
// (tcgen05 unavailable: harness PTX target is plain sm_103)
// ============================================================

#define BATCH   4096
#define IN_DIM  4096
#define OUT_DIM 4096

__device__ __nv_bfloat16 g_xhi[(size_t)BATCH * IN_DIM];
__device__ __nv_bfloat16 g_xlo[(size_t)BATCH * IN_DIM];
__device__ __nv_bfloat16 g_whi[(size_t)OUT_DIM * IN_DIM];
__device__ __nv_bfloat16 g_wlo[(size_t)OUT_DIM * IN_DIM];

// ---------------- PTX helpers ----------------
__device__ __forceinline__ uint32_t smem_to_u32(const void* p) {
    uint32_t a;
    asm("{ .reg .u64 t; cvta.to.shared.u64 t, %1; cvt.u32.u64 %0, t; }" : "=r"(a) : "l"(p));
    return a;
}

__device__ __forceinline__ void cp16(uint32_t dst, const void* src) {
    asm volatile("cp.async.cg.shared.global [%0], [%1], 16;"
                 :: "r"(dst), "l"(__cvta_generic_to_global(src)) : "memory");
}

#define CP_COMMIT() asm volatile("cp.async.commit_group;" ::: "memory")
#define CP_WAIT(n)  asm volatile("cp.async.wait_group %0;" :: "n"(n) : "memory")

__device__ __forceinline__ void ldmx4(uint32_t* r, uint32_t addr) {
    asm volatile("ldmatrix.sync.aligned.m8n8.x4.shared.b16 {%0,%1,%2,%3}, [%4];"
                 : "=r"(r[0]), "=r"(r[1]), "=r"(r[2]), "=r"(r[3]) : "r"(addr));
}

__device__ __forceinline__ void mma16816(float* d, const uint32_t* a,
                                         uint32_t b0, uint32_t b1) {
    asm volatile(
        "mma.sync.aligned.m16n8k16.row.col.f32.bf16.bf16.f32 "
        "{%0,%1,%2,%3}, {%4,%5,%6,%7}, {%8,%9}, {%0,%1,%2,%3};"
        : "+f"(d[0]), "+f"(d[1]), "+f"(d[2]), "+f"(d[3])
        : "r"(a[0]), "r"(a[1]), "r"(a[2]), "r"(a[3]), "r"(b0), "r"(b1));
}

// ---------------- split: fp32 -> (bf16 hi, bf16 lo) ----------------
__global__ __launch_bounds__(256) void split_kernel(const float4* __restrict__ src, int which) {
    uint2* hi2 = reinterpret_cast<uint2*>(which ? g_whi : g_xhi);
    uint2* lo2 = reinterpret_cast<uint2*>(which ? g_wlo : g_xlo);
    const int n4 = (int)(((size_t)BATCH * IN_DIM) / 4);
    for (int i = blockIdx.x * blockDim.x + threadIdx.x; i < n4; i += gridDim.x * blockDim.x) {
        float4 v = src[i];
        float f[4] = {v.x, v.y, v.z, v.w};
        uint32_t h[4], l[4];
#pragma unroll
        for (int j = 0; j < 4; j++) {
            __nv_bfloat16 hb = __float2bfloat16(f[j]);
            float r = f[j] - __bfloat162float(hb);
            __nv_bfloat16 lb = __float2bfloat16(r);
            h[j] = (uint32_t)__bfloat16_as_ushort(hb);
            l[j] = (uint32_t)__bfloat16_as_ushort(lb);
        }
        hi2[i] = make_uint2(h[0] | (h[1] << 16), h[2] | (h[3] << 16));
        lo2[i] = make_uint2(l[0] | (l[1] << 16), l[2] | (l[3] << 16));
    }
}

// ---------------- GEMM ----------------
// CTA tile 128(M) x 256(N), 256 threads (8 warps, 2x4), warp tile 64x64.
// K-chunk = 32 bf16, 4-stage cp.async pipeline.
static constexpr int MT = 128;
static constexpr int NT = 256;
static constexpr int KC = 32;
static constexpr int STAGES = 4;
static constexpr int NCHUNK = IN_DIM / KC;              // 128
static constexpr uint32_t ST_A_HI = 0;
static constexpr uint32_t ST_A_LO = 8192;
static constexpr uint32_t ST_B_HI = 16384;
static constexpr uint32_t ST_B_LO = 32768;
static constexpr uint32_t STAGE_BYTES = 49152;          // 48 KB
static constexpr uint32_t SMEM_TOTAL = STAGES * STAGE_BYTES;  // 192 KB

// SMEM tile: row pitch 64B (32 bf16), XOR swizzle: 16B-col ^= (row>>1)&3
__device__ __forceinline__ uint32_t swz(int row, int c16) {
    return (uint32_t)(row * 64 + ((c16 ^ ((row >> 1) & 3)) << 4));
}

__global__ __launch_bounds__(256, 1) void gemm_bf16x3_kernel(const float* __restrict__ bias,
                                                             float* __restrict__ out) {
    extern __shared__ char smem[];
    const uint32_t sb = smem_to_u32(smem);
    const int tid = threadIdx.x;
    const int wid = tid >> 5;
    const int lid = tid & 31;
    const int wm = wid >> 2;          // 0..1 : M warp
    const int wn = wid & 3;           // 0..3 : N warp
    const int m0 = blockIdx.y * MT;
    const int n0 = blockIdx.x * NT;

    // ---- producer per-thread precompute ----
    // A tile: 128 rows x 4 c16-cols = 512 items (2 iters of 256 threads)
    // B tile: 256 rows x 4 c16-cols = 1024 items (4 iters)
    const __nv_bfloat16* xhi = g_xhi + (size_t)m0 * IN_DIM;
    const __nv_bfloat16* xlo = g_xlo + (size_t)m0 * IN_DIM;
    const __nv_bfloat16* whi = g_whi + (size_t)n0 * IN_DIM;
    const __nv_bfloat16* wlo = g_wlo + (size_t)n0 * IN_DIM;

    uint32_t aDst[2], bDst[4];
    size_t   aSrc[2], bSrc[4];
#pragma unroll
    for (int i = 0; i < 2; i++) {
        int o = tid + i * 256, row = o >> 2, c16 = o & 3;
        aDst[i] = swz(row, c16);
        aSrc[i] = (size_t)row * IN_DIM + c16 * 8;
    }
#pragma unroll
    for (int i = 0; i < 4; i++) {
        int o = tid + i * 256, row = o >> 2, c16 = o & 3;
        bDst[i] = swz(row, c16);
        bSrc[i] = (size_t)row * IN_DIM + c16 * 8;
    }

    // ---- ldmatrix per-thread precompute ----
    const int lrow = lid & 15;        // row within 16-row tile
    const int lcol = lid >> 4;        // 16B col selector (0/1)
    uint32_t aOff[4], aXr[4], bOff[4], bXr[4];
#pragma unroll
    for (int mt = 0; mt < 4; mt++) {
        int r = wm * 64 + mt * 16 + lrow;
        aOff[mt] = (uint32_t)(r * 64);
        aXr[mt] = (uint32_t)((r >> 1) & 3);
    }
#pragma unroll
    for (int nt2 = 0; nt2 < 4; nt2++) {
        int r = wn * 64 + nt2 * 16 + lrow;
        bOff[nt2] = (uint32_t)(r * 64);
        bXr[nt2] = (uint32_t)((r >> 1) & 3);
    }

    float acc[4][8][4];
#pragma unroll
    for (int mt = 0; mt < 4; mt++)
#pragma unroll
        for (int nt = 0; nt < 8; nt++)
#pragma unroll
            for (int j = 0; j < 4; j++) acc[mt][nt][j] = 0.0f;

    // ---- prologue: fill STAGES-1 stages ----
#pragma unroll
    for (int c = 0; c < STAGES - 1; c++) {
        const uint32_t stg = sb + (uint32_t)c * STAGE_BYTES;
        const int k0 = c * KC;
#pragma unroll
        for (int i = 0; i < 2; i++) {
            cp16(stg + ST_A_HI + aDst[i], xhi + aSrc[i] + k0);
            cp16(stg + ST_A_LO + aDst[i], xlo + aSrc[i] + k0);
        }
#pragma unroll
        for (int i = 0; i < 4; i++) {
            cp16(stg + ST_B_HI + bDst[i], whi + bSrc[i] + k0);
            cp16(stg + ST_B_LO + bDst[i], wlo + bSrc[i] + k0);
        }
        CP_COMMIT();
    }

    // ---- mainloop ----
    for (int c = 0; c < NCHUNK; c++) {
        CP_WAIT(STAGES - 2);
        __syncthreads();

        // issue loads for chunk c+3
        if (c + STAGES - 1 < NCHUNK) {
            const int cl = c + STAGES - 1;
            const uint32_t stg = sb + (uint32_t)(cl & (STAGES - 1)) * STAGE_BYTES;
            const int k0 = cl * KC;
#pragma unroll
            for (int i = 0; i < 2; i++) {
                cp16(stg + ST_A_HI + aDst[i], xhi + aSrc[i] + k0);
                cp16(stg + ST_A_LO + aDst[i], xlo + aSrc[i] + k0);
            }
#pragma unroll
            for (int i = 0; i < 4; i++) {
                cp16(stg + ST_B_HI + bDst[i], whi + bSrc[i] + k0);
                cp16(stg + ST_B_LO + bDst[i], wlo + bSrc[i] + k0);
            }
        }
        CP_COMMIT();

        // compute on stage c
        const uint32_t stg = sb + (uint32_t)(c & (STAGES - 1)) * STAGE_BYTES;
#pragma unroll
        for (int ks = 0; ks < 2; ks++) {
            const uint32_t kc = (uint32_t)(ks * 2 + lcol);
            uint32_t ah[4][4], al[4][4];
#pragma unroll
            for (int mt = 0; mt < 4; mt++) {
                uint32_t ad = stg + aOff[mt] + ((kc ^ aXr[mt]) << 4);
                ldmx4(ah[mt], ad + ST_A_HI);
                ldmx4(al[mt], ad + ST_A_LO);
            }
#pragma unroll
            for (int nt2 = 0; nt2 < 4; nt2++) {
                uint32_t bd = stg + bOff[nt2] + ((kc ^ bXr[nt2]) << 4);
                uint32_t bh[4], bl[4];
                ldmx4(bh, bd + ST_B_HI);
                ldmx4(bl, bd + ST_B_LO);
                // ldmatrix.x4 matrices: {r0,r2} = frag ntile even, {r1,r3} = ntile odd
#pragma unroll
                for (int mt = 0; mt < 4; mt++) {
                    mma16816(acc[mt][nt2 * 2],     ah[mt], bh[0], bh[2]);
                    mma16816(acc[mt][nt2 * 2 + 1], ah[mt], bh[1], bh[3]);
                    mma16816(acc[mt][nt2 * 2],     ah[mt], bl[0], bl[2]);
                    mma16816(acc[mt][nt2 * 2 + 1], ah[mt], bl[1], bl[3]);
                    mma16816(acc[mt][nt2 * 2],     al[mt], bh[0], bh[2]);
                    mma16816(acc[mt][nt2 * 2 + 1], al[mt], bh[1], bh[3]);
                }
            }
        }
    }

    // ---- epilogue: bias + direct float2 stores (32B-sector aligned groups) ----
    const int gr = lid >> 2;          // row-in-tile 0..7
    const int gc = (lid & 3) * 2;     // col pair
#pragma unroll
    for (int mt = 0; mt < 4; mt++) {
        const int rbase = m0 + wm * 64 + mt * 16 + gr;
#pragma unroll
        for (int nt = 0; nt < 8; nt++) {
            const int col = n0 + wn * 64 + nt * 8 + gc;
            const float b0 = __ldg(bias + col);
            const float b1 = __ldg(bias + col + 1);
            float2 v0 = make_float2(acc[mt][nt][0] + b0, acc[mt][nt][1] + b1);
            float2 v1 = make_float2(acc[mt][nt][2] + b0, acc[mt][nt][3] + b1);
            *reinterpret_cast<float2*>(out + (size_t)rbase * OUT_DIM + col) = v0;
            *reinterpret_cast<float2*>(out + (size_t)(rbase + 8) * OUT_DIM + col) = v1;
        }
    }
}

// ---------------- launch ----------------
extern "C" void kernel_launch(void* const* d_in, const int* in_sizes, int n_in,
                              void* d_out, int out_size) {
    (void)in_sizes; (void)n_in; (void)out_size;
    const float* x = (const float*)d_in[0];
    const float* W = (const float*)d_in[1];
    const float* b = (const float*)d_in[2];
    float* out = (float*)d_out;

    split_kernel<<<2048, 256>>>((const float4*)x, 0);
    split_kernel<<<2048, 256>>>((const float4*)W, 1);

    cudaFuncSetAttribute(gemm_bf16x3_kernel,
                         cudaFuncAttributeMaxDynamicSharedMemorySize, SMEM_TOTAL);
    dim3 grid(OUT_DIM / NT, BATCH / MT);  // (16, 32)
    gemm_bf16x3_kernel<<<grid, 256, SMEM_TOTAL>>>(b, out);
}

// round 5
// speedup vs baseline: 1.4803x; 1.4803x over previous
#include <cuda_runtime.h>
#include <cuda_fp16.h>
#include <cstdint>

// ============================================================
// out[4096,4096] = x[4096,4096] @ W^T[4096,4096] + b
// fp16 2-GEMM scheme:  out ≈ xh @ Whi^T + xh @ Wlo^T + b
//   xh  = fp16(x)                  (dropped xlo -> rel err ~2.8e-4)
//   Whi = fp16(W), Wlo = fp16(W - Whi)
// mma.sync HMMA (tcgen05 unavailable: PTX target is plain sm_103)
// ============================================================

#define BATCH   4096
#define IN_DIM  4096
#define OUT_DIM 4096

__device__ __half g_xh[(size_t)BATCH * IN_DIM];
__device__ __half g_wh[(size_t)OUT_DIM * IN_DIM];
__device__ __half g_wl[(size_t)OUT_DIM * IN_DIM];

// ---------------- PTX helpers ----------------
__device__ __forceinline__ uint32_t smem_to_u32(const void* p) {
    uint32_t a;
    asm("{ .reg .u64 t; cvta.to.shared.u64 t, %1; cvt.u32.u64 %0, t; }" : "=r"(a) : "l"(p));
    return a;
}

__device__ __forceinline__ void cp16(uint32_t dst, const void* src) {
    asm volatile("cp.async.cg.shared.global [%0], [%1], 16;"
                 :: "r"(dst), "l"(__cvta_generic_to_global(src)) : "memory");
}

#define CP_COMMIT() asm volatile("cp.async.commit_group;" ::: "memory")
#define CP_WAIT(n)  asm volatile("cp.async.wait_group %0;" :: "n"(n) : "memory")

__device__ __forceinline__ void ldmx4(uint32_t* r, uint32_t addr) {
    asm volatile("ldmatrix.sync.aligned.m8n8.x4.shared.b16 {%0,%1,%2,%3}, [%4];"
                 : "=r"(r[0]), "=r"(r[1]), "=r"(r[2]), "=r"(r[3]) : "r"(addr));
}

__device__ __forceinline__ void mma16816(float* d, const uint32_t* a,
                                         uint32_t b0, uint32_t b1) {
    asm volatile(
        "mma.sync.aligned.m16n8k16.row.col.f32.f16.f16.f32 "
        "{%0,%1,%2,%3}, {%4,%5,%6,%7}, {%8,%9}, {%0,%1,%2,%3};"
        : "+f"(d[0]), "+f"(d[1]), "+f"(d[2]), "+f"(d[3])
        : "r"(a[0]), "r"(a[1]), "r"(a[2]), "r"(a[3]), "r"(b0), "r"(b1));
}

// ---------------- split kernels ----------------
// which=0: x -> g_xh (fp16 single)
// which=1: W -> g_wh (fp16 hi) + g_wl (fp16 residual)
__global__ __launch_bounds__(256) void split_kernel(const float4* __restrict__ src, int which) {
    const int n4 = (int)(((size_t)BATCH * IN_DIM) / 4);
    if (which == 0) {
        uint2* dst = reinterpret_cast<uint2*>(g_xh);
        for (int i = blockIdx.x * blockDim.x + threadIdx.x; i < n4; i += gridDim.x * blockDim.x) {
            float4 v = src[i];
            __half2 p0 = make_half2(__float2half_rn(v.x), __float2half_rn(v.y));
            __half2 p1 = make_half2(__float2half_rn(v.z), __float2half_rn(v.w));
            dst[i] = make_uint2(*reinterpret_cast<uint32_t*>(&p0),
                                *reinterpret_cast<uint32_t*>(&p1));
        }
    } else {
        uint2* hi2 = reinterpret_cast<uint2*>(g_wh);
        uint2* lo2 = reinterpret_cast<uint2*>(g_wl);
        for (int i = blockIdx.x * blockDim.x + threadIdx.x; i < n4; i += gridDim.x * blockDim.x) {
            float4 v = src[i];
            float f[4] = {v.x, v.y, v.z, v.w};
            uint32_t h[4], l[4];
#pragma unroll
            for (int j = 0; j < 4; j++) {
                __half hb = __float2half_rn(f[j]);
                float r = f[j] - __half2float(hb);
                __half lb = __float2half_rn(r);
                h[j] = (uint32_t)__half_as_ushort(hb);
                l[j] = (uint32_t)__half_as_ushort(lb);
            }
            hi2[i] = make_uint2(h[0] | (h[1] << 16), h[2] | (h[3] << 16));
            lo2[i] = make_uint2(l[0] | (l[1] << 16), l[2] | (l[3] << 16));
        }
    }
}

// ---------------- GEMM ----------------
// CTA tile 128(M) x 256(N), 256 threads (8 warps, 2x4), warp tile 64x64.
// K-chunk = 32 fp16, 5-stage cp.async pipeline (40 KB/stage).
static constexpr int MT = 128;
static constexpr int NT = 256;
static constexpr int KC = 32;
static constexpr int STAGES = 5;
static constexpr int NCHUNK = IN_DIM / KC;              // 128
static constexpr uint32_t ST_A    = 0;                  // 128 rows x 64B = 8 KB
static constexpr uint32_t ST_B_HI = 8192;               // 256 rows x 64B = 16 KB
static constexpr uint32_t ST_B_LO = 24576;              // 16 KB
static constexpr uint32_t STAGE_BYTES = 40960;
static constexpr uint32_t SMEM_TOTAL = STAGES * STAGE_BYTES;  // 200 KB

// SMEM tile: row pitch 64B (32 fp16), XOR swizzle: 16B-col ^= (row>>1)&3
__device__ __forceinline__ uint32_t swz(int row, int c16) {
    return (uint32_t)(row * 64 + ((c16 ^ ((row >> 1) & 3)) << 4));
}

__global__ __launch_bounds__(256, 1) void gemm_fp16x2_kernel(const float* __restrict__ bias,
                                                             float* __restrict__ out) {
    extern __shared__ char smem[];
    const uint32_t sb = smem_to_u32(smem);
    const int tid = threadIdx.x;
    const int wid = tid >> 5;
    const int lid = tid & 31;
    const int wm = wid >> 2;          // 0..1 : M warp
    const int wn = wid & 3;           // 0..3 : N warp
    const int m0 = blockIdx.y * MT;
    const int n0 = blockIdx.x * NT;

    const __half* xh = g_xh + (size_t)m0 * IN_DIM;
    const __half* wh = g_wh + (size_t)n0 * IN_DIM;
    const __half* wl = g_wl + (size_t)n0 * IN_DIM;

    // ---- producer per-thread precompute ----
    uint32_t aDst[2], bDst[4];
    size_t   aSrc[2], bSrc[4];
#pragma unroll
    for (int i = 0; i < 2; i++) {
        int o = tid + i * 256, row = o >> 2, c16 = o & 3;
        aDst[i] = swz(row, c16);
        aSrc[i] = (size_t)row * IN_DIM + c16 * 8;
    }
#pragma unroll
    for (int i = 0; i < 4; i++) {
        int o = tid + i * 256, row = o >> 2, c16 = o & 3;
        bDst[i] = swz(row, c16);
        bSrc[i] = (size_t)row * IN_DIM + c16 * 8;
    }

    // ---- ldmatrix per-thread precompute ----
    const int lrow = lid & 15;
    const int lcol = lid >> 4;
    uint32_t aOff[4], aXr[4], bOff[4], bXr[4];
#pragma unroll
    for (int mt = 0; mt < 4; mt++) {
        int r = wm * 64 + mt * 16 + lrow;
        aOff[mt] = (uint32_t)(r * 64);
        aXr[mt]  = (uint32_t)((r >> 1) & 3);
    }
#pragma unroll
    for (int nt2 = 0; nt2 < 4; nt2++) {
        int r = wn * 64 + nt2 * 16 + lrow;
        bOff[nt2] = (uint32_t)(r * 64);
        bXr[nt2]  = (uint32_t)((r >> 1) & 3);
    }

    float acc[4][8][4];
#pragma unroll
    for (int mt = 0; mt < 4; mt++)
#pragma unroll
        for (int nt = 0; nt < 8; nt++)
#pragma unroll
            for (int j = 0; j < 4; j++) acc[mt][nt][j] = 0.0f;

    // ---- prologue: fill STAGES-1 stages ----
#pragma unroll
    for (int c = 0; c < STAGES - 1; c++) {
        const uint32_t stg = sb + (uint32_t)c * STAGE_BYTES;
        const int k0 = c * KC;
#pragma unroll
        for (int i = 0; i < 2; i++)
            cp16(stg + ST_A + aDst[i], xh + aSrc[i] + k0);
#pragma unroll
        for (int i = 0; i < 4; i++) {
            cp16(stg + ST_B_HI + bDst[i], wh + bSrc[i] + k0);
            cp16(stg + ST_B_LO + bDst[i], wl + bSrc[i] + k0);
        }
        CP_COMMIT();
    }

    // ---- mainloop ----
    int s_cons = 0, s_prod = STAGES - 1;
    for (int c = 0; c < NCHUNK; c++) {
        CP_WAIT(STAGES - 2);
        __syncthreads();

        // issue loads for chunk c + STAGES-1
        if (c + STAGES - 1 < NCHUNK) {
            const uint32_t stg = sb + (uint32_t)s_prod * STAGE_BYTES;
            const int k0 = (c + STAGES - 1) * KC;
#pragma unroll
            for (int i = 0; i < 2; i++)
                cp16(stg + ST_A + aDst[i], xh + aSrc[i] + k0);
#pragma unroll
            for (int i = 0; i < 4; i++) {
                cp16(stg + ST_B_HI + bDst[i], wh + bSrc[i] + k0);
                cp16(stg + ST_B_LO + bDst[i], wl + bSrc[i] + k0);
            }
        }
        CP_COMMIT();

        // compute on stage s_cons
        const uint32_t stg = sb + (uint32_t)s_cons * STAGE_BYTES;
#pragma unroll
        for (int ks = 0; ks < 2; ks++) {
            const uint32_t kc = (uint32_t)(ks * 2 + lcol);
            uint32_t ah[4][4];
#pragma unroll
            for (int mt = 0; mt < 4; mt++)
                ldmx4(ah[mt], stg + ST_A + aOff[mt] + ((kc ^ aXr[mt]) << 4));
#pragma unroll
            for (int nt2 = 0; nt2 < 4; nt2++) {
                uint32_t bd = stg + bOff[nt2] + ((kc ^ bXr[nt2]) << 4);
                uint32_t bh[4], bl[4];
                ldmx4(bh, bd + ST_B_HI);
                ldmx4(bl, bd + ST_B_LO);
                // ldmatrix.x4: {r0,r2} = even n-tile frag, {r1,r3} = odd
#pragma unroll
                for (int mt = 0; mt < 4; mt++) {
                    mma16816(acc[mt][nt2 * 2],     ah[mt], bh[0], bh[2]);
                    mma16816(acc[mt][nt2 * 2 + 1], ah[mt], bh[1], bh[3]);
                    mma16816(acc[mt][nt2 * 2],     ah[mt], bl[0], bl[2]);
                    mma16816(acc[mt][nt2 * 2 + 1], ah[mt], bl[1], bl[3]);
                }
            }
        }
        if (++s_cons == STAGES) s_cons = 0;
        if (++s_prod == STAGES) s_prod = 0;
    }

    // ---- epilogue: bias + direct float2 stores ----
    const int gr = lid >> 2;
    const int gc = (lid & 3) * 2;
#pragma unroll
    for (int mt = 0; mt < 4; mt++) {
        const int rbase = m0 + wm * 64 + mt * 16 + gr;
#pragma unroll
        for (int nt = 0; nt < 8; nt++) {
            const int col = n0 + wn * 64 + nt * 8 + gc;
            const float b0 = __ldg(bias + col);
            const float b1 = __ldg(bias + col + 1);
            float2 v0 = make_float2(acc[mt][nt][0] + b0, acc[mt][nt][1] + b1);
            float2 v1 = make_float2(acc[mt][nt][2] + b0, acc[mt][nt][3] + b1);
            *reinterpret_cast<float2*>(out + (size_t)rbase * OUT_DIM + col) = v0;
            *reinterpret_cast<float2*>(out + (size_t)(rbase + 8) * OUT_DIM + col) = v1;
        }
    }
}

// ---------------- launch ----------------
extern "C" void kernel_launch(void* const* d_in, const int* in_sizes, int n_in,
                              void* d_out, int out_size) {
    (void)in_sizes; (void)n_in; (void)out_size;
    const float* x = (const float*)d_in[0];
    const float* W = (const float*)d_in[1];
    const float* b = (const float*)d_in[2];
    float* out = (float*)d_out;

    split_kernel<<<2048, 256>>>((const float4*)x, 0);
    split_kernel<<<2048, 256>>>((const float4*)W, 1);

    cudaFuncSetAttribute(gemm_fp16x2_kernel,
                         cudaFuncAttributeMaxDynamicSharedMemorySize, SMEM_TOTAL);
    dim3 grid(OUT_DIM / NT, BATCH / MT);  // (16, 32)
    gemm_fp16x2_kernel<<<grid, 256, SMEM_TOTAL>>>(b, out);
}

// round 6
// speedup vs baseline: 2.5568x; 1.7272x over previous
#include <cuda_runtime.h>
#include <cuda_fp16.h>
#include <cstdint>

// ============================================================
// out[4096,4096] = x[4096,4096] @ W^T[4096,4096] + b
// SINGLE fp16 GEMM:  out ≈ fp16(x) @ fp16(W)^T + b
//   error = dropped xlo@W (+2.1e-4) + dropped xh@Wlo (+2.1e-4)
//         ≈ 2.9e-4  (3.4x margin under 1e-3 gate)
// mma.sync HMMA, fp32 accum (tcgen05 unavailable on this target)
// ============================================================

#define BATCH   4096
#define IN_DIM  4096
#define OUT_DIM 4096

__device__ __half g_xh[(size_t)BATCH * IN_DIM];
__device__ __half g_wh[(size_t)OUT_DIM * IN_DIM];

// ---------------- PTX helpers ----------------
__device__ __forceinline__ uint32_t smem_to_u32(const void* p) {
    uint32_t a;
    asm("{ .reg .u64 t; cvta.to.shared.u64 t, %1; cvt.u32.u64 %0, t; }" : "=r"(a) : "l"(p));
    return a;
}

__device__ __forceinline__ void cp16(uint32_t dst, const void* src) {
    asm volatile("cp.async.cg.shared.global [%0], [%1], 16;"
                 :: "r"(dst), "l"(__cvta_generic_to_global(src)) : "memory");
}

#define CP_COMMIT() asm volatile("cp.async.commit_group;" ::: "memory")
#define CP_WAIT(n)  asm volatile("cp.async.wait_group %0;" :: "n"(n) : "memory")

__device__ __forceinline__ void ldmx4(uint32_t* r, uint32_t addr) {
    asm volatile("ldmatrix.sync.aligned.m8n8.x4.shared.b16 {%0,%1,%2,%3}, [%4];"
                 : "=r"(r[0]), "=r"(r[1]), "=r"(r[2]), "=r"(r[3]) : "r"(addr));
}

__device__ __forceinline__ void mma16816(float* d, const uint32_t* a,
                                         uint32_t b0, uint32_t b1) {
    asm volatile(
        "mma.sync.aligned.m16n8k16.row.col.f32.f16.f16.f32 "
        "{%0,%1,%2,%3}, {%4,%5,%6,%7}, {%8,%9}, {%0,%1,%2,%3};"
        : "+f"(d[0]), "+f"(d[1]), "+f"(d[2]), "+f"(d[3])
        : "r"(a[0]), "r"(a[1]), "r"(a[2]), "r"(a[3]), "r"(b0), "r"(b1));
}

// ---------------- convert: fp32 -> fp16 ----------------
// which=0: x -> g_xh ; which=1: W -> g_wh
__global__ __launch_bounds__(256) void cvt_kernel(const float4* __restrict__ src, int which) {
    uint2* dst = reinterpret_cast<uint2*>(which ? g_wh : g_xh);
    const int n4 = (int)(((size_t)BATCH * IN_DIM) / 4);
    for (int i = blockIdx.x * blockDim.x + threadIdx.x; i < n4; i += gridDim.x * blockDim.x) {
        float4 v = src[i];
        __half2 p0 = make_half2(__float2half_rn(v.x), __float2half_rn(v.y));
        __half2 p1 = make_half2(__float2half_rn(v.z), __float2half_rn(v.w));
        dst[i] = make_uint2(*reinterpret_cast<uint32_t*>(&p0),
                            *reinterpret_cast<uint32_t*>(&p1));
    }
}

// ---------------- GEMM ----------------
// CTA tile 128(M) x 256(N), 256 threads (8 warps, 2x4), warp tile 64x64.
// K-chunk = 32 fp16, 8-stage cp.async pipeline (24 KB/stage, 192 KB total).
static constexpr int MT = 128;
static constexpr int NT = 256;
static constexpr int KC = 32;
static constexpr int STAGES = 8;
static constexpr int NCHUNK = IN_DIM / KC;              // 128
static constexpr uint32_t ST_A = 0;                     // 128 rows x 64B = 8 KB
static constexpr uint32_t ST_B = 8192;                  // 256 rows x 64B = 16 KB
static constexpr uint32_t STAGE_BYTES = 24576;
static constexpr uint32_t SMEM_TOTAL = STAGES * STAGE_BYTES;  // 192 KB

// SMEM tile: row pitch 64B (32 fp16), XOR swizzle: 16B-col ^= (row>>1)&3
__device__ __forceinline__ uint32_t swz(int row, int c16) {
    return (uint32_t)(row * 64 + ((c16 ^ ((row >> 1) & 3)) << 4));
}

__global__ __launch_bounds__(256, 1) void gemm_fp16_kernel(const float* __restrict__ bias,
                                                           float* __restrict__ out) {
    extern __shared__ char smem[];
    const uint32_t sb = smem_to_u32(smem);
    const int tid = threadIdx.x;
    const int wid = tid >> 5;
    const int lid = tid & 31;
    const int wm = wid >> 2;          // 0..1 : M warp
    const int wn = wid & 3;           // 0..3 : N warp
    const int m0 = blockIdx.y * MT;
    const int n0 = blockIdx.x * NT;

    const __half* xh = g_xh + (size_t)m0 * IN_DIM;
    const __half* wh = g_wh + (size_t)n0 * IN_DIM;

    // ---- producer per-thread precompute ----
    uint32_t aDst[2], bDst[4];
    size_t   aSrc[2], bSrc[4];
#pragma unroll
    for (int i = 0; i < 2; i++) {
        int o = tid + i * 256, row = o >> 2, c16 = o & 3;
        aDst[i] = swz(row, c16);
        aSrc[i] = (size_t)row * IN_DIM + c16 * 8;
    }
#pragma unroll
    for (int i = 0; i < 4; i++) {
        int o = tid + i * 256, row = o >> 2, c16 = o & 3;
        bDst[i] = swz(row, c16);
        bSrc[i] = (size_t)row * IN_DIM + c16 * 8;
    }

    // ---- ldmatrix per-thread precompute ----
    const int lrow = lid & 15;
    const int lcol = lid >> 4;
    uint32_t aOff[4], aXr[4], bOff[4], bXr[4];
#pragma unroll
    for (int mt = 0; mt < 4; mt++) {
        int r = wm * 64 + mt * 16 + lrow;
        aOff[mt] = (uint32_t)(r * 64);
        aXr[mt]  = (uint32_t)((r >> 1) & 3);
    }
#pragma unroll
    for (int nt2 = 0; nt2 < 4; nt2++) {
        int r = wn * 64 + nt2 * 16 + lrow;
        bOff[nt2] = (uint32_t)(r * 64);
        bXr[nt2]  = (uint32_t)((r >> 1) & 3);
    }

    float acc[4][8][4];
#pragma unroll
    for (int mt = 0; mt < 4; mt++)
#pragma unroll
        for (int nt = 0; nt < 8; nt++)
#pragma unroll
            for (int j = 0; j < 4; j++) acc[mt][nt][j] = 0.0f;

    // ---- prologue: fill STAGES-1 stages ----
#pragma unroll
    for (int c = 0; c < STAGES - 1; c++) {
        const uint32_t stg = sb + (uint32_t)c * STAGE_BYTES;
        const int k0 = c * KC;
#pragma unroll
        for (int i = 0; i < 2; i++)
            cp16(stg + ST_A + aDst[i], xh + aSrc[i] + k0);
#pragma unroll
        for (int i = 0; i < 4; i++)
            cp16(stg + ST_B + bDst[i], wh + bSrc[i] + k0);
        CP_COMMIT();
    }

    // ---- mainloop ----
    for (int c = 0; c < NCHUNK; c++) {
        CP_WAIT(STAGES - 2);
        __syncthreads();

        // issue loads for chunk c + STAGES-1 into stage (c-1) & 7
        if (c + STAGES - 1 < NCHUNK) {
            const uint32_t stg = sb + (uint32_t)((c + STAGES - 1) & (STAGES - 1)) * STAGE_BYTES;
            const int k0 = (c + STAGES - 1) * KC;
#pragma unroll
            for (int i = 0; i < 2; i++)
                cp16(stg + ST_A + aDst[i], xh + aSrc[i] + k0);
#pragma unroll
            for (int i = 0; i < 4; i++)
                cp16(stg + ST_B + bDst[i], wh + bSrc[i] + k0);
        }
        CP_COMMIT();

        // compute on stage c & 7
        const uint32_t stg = sb + (uint32_t)(c & (STAGES - 1)) * STAGE_BYTES;
#pragma unroll
        for (int ks = 0; ks < 2; ks++) {
            const uint32_t kc = (uint32_t)(ks * 2 + lcol);
            uint32_t ah[4][4];
#pragma unroll
            for (int mt = 0; mt < 4; mt++)
                ldmx4(ah[mt], stg + ST_A + aOff[mt] + ((kc ^ aXr[mt]) << 4));
#pragma unroll
            for (int nt2 = 0; nt2 < 4; nt2++) {
                uint32_t bh[4];
                ldmx4(bh, stg + ST_B + bOff[nt2] + ((kc ^ bXr[nt2]) << 4));
                // ldmatrix.x4: {r0,r2} = even n-tile frag, {r1,r3} = odd
#pragma unroll
                for (int mt = 0; mt < 4; mt++) {
                    mma16816(acc[mt][nt2 * 2],     ah[mt], bh[0], bh[2]);
                    mma16816(acc[mt][nt2 * 2 + 1], ah[mt], bh[1], bh[3]);
                }
            }
        }
    }

    // ---- epilogue: bias + direct float2 stores ----
    const int gr = lid >> 2;
    const int gc = (lid & 3) * 2;
#pragma unroll
    for (int mt = 0; mt < 4; mt++) {
        const int rbase = m0 + wm * 64 + mt * 16 + gr;
#pragma unroll
        for (int nt = 0; nt < 8; nt++) {
            const int col = n0 + wn * 64 + nt * 8 + gc;
            const float b0 = __ldg(bias + col);
            const float b1 = __ldg(bias + col + 1);
            float2 v0 = make_float2(acc[mt][nt][0] + b0, acc[mt][nt][1] + b1);
            float2 v1 = make_float2(acc[mt][nt][2] + b0, acc[mt][nt][3] + b1);
            *reinterpret_cast<float2*>(out + (size_t)rbase * OUT_DIM + col) = v0;
            *reinterpret_cast<float2*>(out + (size_t)(rbase + 8) * OUT_DIM + col) = v1;
        }
    }
}

// ---------------- launch ----------------
extern "C" void kernel_launch(void* const* d_in, const int* in_sizes, int n_in,
                              void* d_out, int out_size) {
    (void)in_sizes; (void)n_in; (void)out_size;
    const float* x = (const float*)d_in[0];
    const float* W = (const float*)d_in[1];
    const float* b = (const float*)d_in[2];
    float* out = (float*)d_out;

    cvt_kernel<<<2048, 256>>>((const float4*)x, 0);
    cvt_kernel<<<2048, 256>>>((const float4*)W, 1);

    cudaFuncSetAttribute(gemm_fp16_kernel,
                         cudaFuncAttributeMaxDynamicSharedMemorySize, SMEM_TOTAL);
    dim3 grid(OUT_DIM / NT, BATCH / MT);  // (16, 32)
    gemm_fp16_kernel<<<grid, 256, SMEM_TOTAL>>>(b, out);
}

// round 7
// speedup vs baseline: 2.8931x; 1.1315x over previous
#include <cuda_runtime.h>
#include <cuda_fp16.h>
#include <cstdint>

// ============================================================
// out[4096,4096] = x[4096,4096] @ W^T[4096,4096] + b
// SINGLE fp16 GEMM:  out ≈ fp16(x) @ fp16(W)^T + b  (rel_err ~2.8e-4)
// mma.sync HMMA fp32-acc; KC=64, reg-double-buffered inner pipeline
// ============================================================

#define BATCH   4096
#define IN_DIM  4096
#define OUT_DIM 4096

__device__ __half g_xh[(size_t)BATCH * IN_DIM];
__device__ __half g_wh[(size_t)OUT_DIM * IN_DIM];

// ---------------- PTX helpers ----------------
__device__ __forceinline__ uint32_t smem_to_u32(const void* p) {
    uint32_t a;
    asm("{ .reg .u64 t; cvta.to.shared.u64 t, %1; cvt.u32.u64 %0, t; }" : "=r"(a) : "l"(p));
    return a;
}

__device__ __forceinline__ void cp16(uint32_t dst, const void* src) {
    asm volatile("cp.async.cg.shared.global [%0], [%1], 16;"
                 :: "r"(dst), "l"(__cvta_generic_to_global(src)) : "memory");
}

#define CP_COMMIT() asm volatile("cp.async.commit_group;" ::: "memory")
#define CP_WAIT(n)  asm volatile("cp.async.wait_group %0;" :: "n"(n) : "memory")

__device__ __forceinline__ void ldmx4(uint32_t* r, uint32_t addr) {
    asm volatile("ldmatrix.sync.aligned.m8n8.x4.shared.b16 {%0,%1,%2,%3}, [%4];"
                 : "=r"(r[0]), "=r"(r[1]), "=r"(r[2]), "=r"(r[3]) : "r"(addr));
}

__device__ __forceinline__ void mma16816(float* d, const uint32_t* a,
                                         uint32_t b0, uint32_t b1) {
    asm volatile(
        "mma.sync.aligned.m16n8k16.row.col.f32.f16.f16.f32 "
        "{%0,%1,%2,%3}, {%4,%5,%6,%7}, {%8,%9}, {%0,%1,%2,%3};"
        : "+f"(d[0]), "+f"(d[1]), "+f"(d[2]), "+f"(d[3])
        : "r"(a[0]), "r"(a[1]), "r"(a[2]), "r"(a[3]), "r"(b0), "r"(b1));
}

// ---------------- convert: fp32 -> fp16 (x and W in one kernel) ----------------
__global__ __launch_bounds__(256) void cvt_kernel(const float4* __restrict__ x,
                                                  const float4* __restrict__ w) {
    const int n4 = (int)(((size_t)BATCH * IN_DIM) / 4);
    uint2* xh = reinterpret_cast<uint2*>(g_xh);
    uint2* wh = reinterpret_cast<uint2*>(g_wh);
    const int stride = gridDim.x * blockDim.x;
    for (int i = blockIdx.x * blockDim.x + threadIdx.x; i < 2 * n4; i += stride) {
        const bool isW = (i >= n4);
        const int j = isW ? i - n4 : i;
        float4 v = isW ? w[j] : x[j];
        __half2 p0 = make_half2(__float2half_rn(v.x), __float2half_rn(v.y));
        __half2 p1 = make_half2(__float2half_rn(v.z), __float2half_rn(v.w));
        uint2 r = make_uint2(*reinterpret_cast<uint32_t*>(&p0),
                             *reinterpret_cast<uint32_t*>(&p1));
        if (isW) wh[j] = r; else xh[j] = r;
    }
}

// ---------------- GEMM ----------------
// CTA tile 128(M) x 256(N), 256 threads (8 warps, 2x4), warp tile 64x64.
// K-chunk = 64 fp16, 4-stage cp.async pipeline (48 KB/stage, 192 KB total).
static constexpr int MT = 128;
static constexpr int NT = 256;
static constexpr int KC = 64;
static constexpr int STAGES = 4;
static constexpr int NCHUNK = IN_DIM / KC;              // 64
static constexpr uint32_t ST_A = 0;                     // 128 rows x 128B = 16 KB
static constexpr uint32_t ST_B = 16384;                 // 256 rows x 128B = 32 KB
static constexpr uint32_t STAGE_BYTES = 49152;          // 48 KB
static constexpr uint32_t SMEM_TOTAL = STAGES * STAGE_BYTES;  // 192 KB

// SMEM tile: row pitch 128B (64 fp16), SW128-style swizzle: 16B-col ^= row&7
__device__ __forceinline__ uint32_t swz(int row, int c16) {
    return (uint32_t)(row * 128 + ((c16 ^ (row & 7)) << 4));
}

__global__ __launch_bounds__(256, 1) void gemm_fp16_kernel(const float* __restrict__ bias,
                                                           float* __restrict__ out) {
    extern __shared__ char smem[];
    const uint32_t sb = smem_to_u32(smem);
    const int tid = threadIdx.x;
    const int wid = tid >> 5;
    const int lid = tid & 31;
    const int wm = wid >> 2;          // 0..1 : M warp
    const int wn = wid & 3;           // 0..3 : N warp
    const int m0 = blockIdx.y * MT;
    const int n0 = blockIdx.x * NT;

    const __half* xh = g_xh + (size_t)m0 * IN_DIM;
    const __half* wh = g_wh + (size_t)n0 * IN_DIM;

    // ---- producer per-thread precompute (KC=64: 8 x 16B per row) ----
    uint32_t aDst[4], bDst[8];
    size_t   aSrc[4], bSrc[8];
#pragma unroll
    for (int i = 0; i < 4; i++) {
        int o = tid + i * 256, row = o >> 3, c16 = o & 7;
        aDst[i] = swz(row, c16);
        aSrc[i] = (size_t)row * IN_DIM + c16 * 8;
    }
#pragma unroll
    for (int i = 0; i < 8; i++) {
        int o = tid + i * 256, row = o >> 3, c16 = o & 7;
        bDst[i] = swz(row, c16);
        bSrc[i] = (size_t)row * IN_DIM + c16 * 8;
    }

    // ---- ldmatrix per-thread precompute ----
    const int lrow = lid & 15;
    const uint32_t lcol = (uint32_t)(lid >> 4);
    uint32_t aOff[4], aXr[4], bOff[4], bXr[4];
#pragma unroll
    for (int mt = 0; mt < 4; mt++) {
        int r = wm * 64 + mt * 16 + lrow;
        aOff[mt] = (uint32_t)(r * 128);
        aXr[mt]  = (uint32_t)(r & 7);
    }
#pragma unroll
    for (int nt2 = 0; nt2 < 4; nt2++) {
        int r = wn * 64 + nt2 * 16 + lrow;
        bOff[nt2] = (uint32_t)(r * 128);
        bXr[nt2]  = (uint32_t)(r & 7);
    }

    float acc[4][8][4];
#pragma unroll
    for (int mt = 0; mt < 4; mt++)
#pragma unroll
        for (int nt = 0; nt < 8; nt++)
#pragma unroll
            for (int j = 0; j < 4; j++) acc[mt][nt][j] = 0.0f;

    // ---- prologue: fill STAGES-1 stages ----
#pragma unroll
    for (int c = 0; c < STAGES - 1; c++) {
        const uint32_t stg = sb + (uint32_t)c * STAGE_BYTES;
        const int k0 = c * KC;
#pragma unroll
        for (int i = 0; i < 4; i++)
            cp16(stg + ST_A + aDst[i], xh + aSrc[i] + k0);
#pragma unroll
        for (int i = 0; i < 8; i++)
            cp16(stg + ST_B + bDst[i], wh + bSrc[i] + k0);
        CP_COMMIT();
    }

    // ---- mainloop ----
    for (int c = 0; c < NCHUNK; c++) {
        CP_WAIT(STAGES - 2);
        __syncthreads();

        // issue loads for chunk c + STAGES-1
        if (c + STAGES - 1 < NCHUNK) {
            const uint32_t stg = sb + (uint32_t)((c + STAGES - 1) & (STAGES - 1)) * STAGE_BYTES;
            const int k0 = (c + STAGES - 1) * KC;
#pragma unroll
            for (int i = 0; i < 4; i++)
                cp16(stg + ST_A + aDst[i], xh + aSrc[i] + k0);
#pragma unroll
            for (int i = 0; i < 8; i++)
                cp16(stg + ST_B + bDst[i], wh + bSrc[i] + k0);
        }
        CP_COMMIT();

        // ---- compute on stage c, software-pipelined over 4 ks ----
        const uint32_t stA = sb + (uint32_t)(c & (STAGES - 1)) * STAGE_BYTES + ST_A;
        const uint32_t stB = sb + (uint32_t)(c & (STAGES - 1)) * STAGE_BYTES + ST_B;

        uint32_t ah[2][4][4];     // A frags, ping-pong across ks
        uint32_t bh[2][4];        // B frag, ping-pong across nt2
#pragma unroll
        for (int mt = 0; mt < 4; mt++)
            ldmx4(ah[0][mt], stA + aOff[mt] + ((lcol ^ aXr[mt]) << 4));
        ldmx4(bh[0], stB + bOff[0] + ((lcol ^ bXr[0]) << 4));

#pragma unroll
        for (int ks = 0; ks < 4; ks++) {
            const uint32_t kc  = (uint32_t)(ks * 2) + lcol;
            const uint32_t kcn = kc + 2;
            const int cur = ks & 1;
#pragma unroll
            for (int nt2 = 0; nt2 < 4; nt2++) {
                const int bcur = nt2 & 1;
                // prefetch next B fragment
                if (nt2 < 3)
                    ldmx4(bh[bcur ^ 1], stB + bOff[nt2 + 1] + ((kc ^ bXr[nt2 + 1]) << 4));
                else if (ks < 3)
                    ldmx4(bh[bcur ^ 1], stB + bOff[0] + ((kcn ^ bXr[0]) << 4));
                // prefetch next ks's A fragments mid-stream
                if (nt2 == 1 && ks < 3) {
#pragma unroll
                    for (int mt = 0; mt < 4; mt++)
                        ldmx4(ah[cur ^ 1][mt], stA + aOff[mt] + ((kcn ^ aXr[mt]) << 4));
                }
                // 8 MMAs on current fragments
#pragma unroll
                for (int mt = 0; mt < 4; mt++) {
                    mma16816(acc[mt][nt2 * 2],     ah[cur][mt], bh[bcur][0], bh[bcur][2]);
                    mma16816(acc[mt][nt2 * 2 + 1], ah[cur][mt], bh[bcur][1], bh[bcur][3]);
                }
            }
        }
    }

    // ---- epilogue: bias + direct float2 stores ----
    const int gr = lid >> 2;
    const int gc = (lid & 3) * 2;
#pragma unroll
    for (int mt = 0; mt < 4; mt++) {
        const int rbase = m0 + wm * 64 + mt * 16 + gr;
#pragma unroll
        for (int nt = 0; nt < 8; nt++) {
            const int col = n0 + wn * 64 + nt * 8 + gc;
            const float b0 = __ldg(bias + col);
            const float b1 = __ldg(bias + col + 1);
            float2 v0 = make_float2(acc[mt][nt][0] + b0, acc[mt][nt][1] + b1);
            float2 v1 = make_float2(acc[mt][nt][2] + b0, acc[mt][nt][3] + b1);
            *reinterpret_cast<float2*>(out + (size_t)rbase * OUT_DIM + col) = v0;
            *reinterpret_cast<float2*>(out + (size_t)(rbase + 8) * OUT_DIM + col) = v1;
        }
    }
}

// ---------------- launch ----------------
extern "C" void kernel_launch(void* const* d_in, const int* in_sizes, int n_in,
                              void* d_out, int out_size) {
    (void)in_sizes; (void)n_in; (void)out_size;
    const float* x = (const float*)d_in[0];
    const float* W = (const float*)d_in[1];
    const float* b = (const float*)d_in[2];
    float* out = (float*)d_out;

    cvt_kernel<<<4096, 256>>>((const float4*)x, (const float4*)W);

    cudaFuncSetAttribute(gemm_fp16_kernel,
                         cudaFuncAttributeMaxDynamicSharedMemorySize, SMEM_TOTAL);
    dim3 grid(OUT_DIM / NT, BATCH / MT);  // (16, 32)
    gemm_fp16_kernel<<<grid, 256, SMEM_TOTAL>>>(b, out);
}

// round 8
// speedup vs baseline: 3.0641x; 1.0591x over previous
#include <cuda_runtime.h>
#include <cuda_fp16.h>
#include <cstdint>

// ============================================================
// out[4096,4096] = x[4096,4096] @ W^T[4096,4096] + b
// SINGLE fp16 GEMM:  out ≈ fp16(x) @ fp16(W)^T + b  (rel_err ~2.8e-4)
// mma.sync HMMA fp32-acc; 512 threads/CTA (4 warps/SMSP) for TLP
// ============================================================

#define BATCH   4096
#define IN_DIM  4096
#define OUT_DIM 4096

__device__ __half g_xh[(size_t)BATCH * IN_DIM];
__device__ __half g_wh[(size_t)OUT_DIM * IN_DIM];

// ---------------- PTX helpers ----------------
__device__ __forceinline__ uint32_t smem_to_u32(const void* p) {
    uint32_t a;
    asm("{ .reg .u64 t; cvta.to.shared.u64 t, %1; cvt.u32.u64 %0, t; }" : "=r"(a) : "l"(p));
    return a;
}

__device__ __forceinline__ void cp16(uint32_t dst, const void* src) {
    asm volatile("cp.async.cg.shared.global [%0], [%1], 16;"
                 :: "r"(dst), "l"(__cvta_generic_to_global(src)) : "memory");
}

#define CP_COMMIT() asm volatile("cp.async.commit_group;" ::: "memory")
#define CP_WAIT(n)  asm volatile("cp.async.wait_group %0;" :: "n"(n) : "memory")

__device__ __forceinline__ void ldmx4(uint32_t* r, uint32_t addr) {
    asm volatile("ldmatrix.sync.aligned.m8n8.x4.shared.b16 {%0,%1,%2,%3}, [%4];"
                 : "=r"(r[0]), "=r"(r[1]), "=r"(r[2]), "=r"(r[3]) : "r"(addr));
}

__device__ __forceinline__ void mma16816(float* d, const uint32_t* a,
                                         uint32_t b0, uint32_t b1) {
    asm volatile(
        "mma.sync.aligned.m16n8k16.row.col.f32.f16.f16.f32 "
        "{%0,%1,%2,%3}, {%4,%5,%6,%7}, {%8,%9}, {%0,%1,%2,%3};"
        : "+f"(d[0]), "+f"(d[1]), "+f"(d[2]), "+f"(d[3])
        : "r"(a[0]), "r"(a[1]), "r"(a[2]), "r"(a[3]), "r"(b0), "r"(b1));
}

// ---------------- convert: fp32 -> fp16 (x and W in one kernel) ----------------
__global__ __launch_bounds__(256) void cvt_kernel(const float4* __restrict__ x,
                                                  const float4* __restrict__ w) {
    const int n4 = (int)(((size_t)BATCH * IN_DIM) / 4);
    uint2* xh = reinterpret_cast<uint2*>(g_xh);
    uint2* wh = reinterpret_cast<uint2*>(g_wh);
    const int stride = gridDim.x * blockDim.x;
    for (int i = blockIdx.x * blockDim.x + threadIdx.x; i < 2 * n4; i += stride) {
        const bool isW = (i >= n4);
        const int j = isW ? i - n4 : i;
        float4 v = isW ? w[j] : x[j];
        __half2 p0 = make_half2(__float2half_rn(v.x), __float2half_rn(v.y));
        __half2 p1 = make_half2(__float2half_rn(v.z), __float2half_rn(v.w));
        uint2 r = make_uint2(*reinterpret_cast<uint32_t*>(&p0),
                             *reinterpret_cast<uint32_t*>(&p1));
        if (isW) wh[j] = r; else xh[j] = r;
    }
}

// ---------------- GEMM ----------------
// CTA tile 128(M) x 256(N), 512 threads (16 warps, 4x4), warp tile 32x64.
// K-chunk = 64 fp16, 4-stage cp.async pipeline (48 KB/stage, 192 KB total).
static constexpr int MT = 128;
static constexpr int NT = 256;
static constexpr int KC = 64;
static constexpr int STAGES = 4;
static constexpr int NCHUNK = IN_DIM / KC;              // 64
static constexpr uint32_t ST_A = 0;                     // 128 rows x 128B = 16 KB
static constexpr uint32_t ST_B = 16384;                 // 256 rows x 128B = 32 KB
static constexpr uint32_t STAGE_BYTES = 49152;          // 48 KB
static constexpr uint32_t SMEM_TOTAL = STAGES * STAGE_BYTES;  // 192 KB

// SMEM tile: row pitch 128B (64 fp16), SW128-style swizzle: 16B-col ^= row&7
__device__ __forceinline__ uint32_t swz(int row, int c16) {
    return (uint32_t)(row * 128 + ((c16 ^ (row & 7)) << 4));
}

__global__ __launch_bounds__(512, 1) void gemm_fp16_kernel(const float* __restrict__ bias,
                                                           float* __restrict__ out) {
    extern __shared__ char smem[];
    const uint32_t sb = smem_to_u32(smem);
    const int tid = threadIdx.x;
    const int wid = tid >> 5;
    const int lid = tid & 31;
    const int wm = wid >> 2;          // 0..3 : M warp (32 rows each)
    const int wn = wid & 3;           // 0..3 : N warp (64 cols each)
    const int m0 = blockIdx.y * MT;
    const int n0 = blockIdx.x * NT;

    const __half* xh = g_xh + (size_t)m0 * IN_DIM;
    const __half* wh = g_wh + (size_t)n0 * IN_DIM;

    // ---- producer per-thread precompute (KC=64: 8 x 16B per row) ----
    uint32_t aDst[2], bDst[4];
    size_t   aSrc[2], bSrc[4];
#pragma unroll
    for (int i = 0; i < 2; i++) {
        int o = tid + i * 512, row = o >> 3, c16 = o & 7;
        aDst[i] = swz(row, c16);
        aSrc[i] = (size_t)row * IN_DIM + c16 * 8;
    }
#pragma unroll
    for (int i = 0; i < 4; i++) {
        int o = tid + i * 512, row = o >> 3, c16 = o & 7;
        bDst[i] = swz(row, c16);
        bSrc[i] = (size_t)row * IN_DIM + c16 * 8;
    }

    // ---- ldmatrix per-thread precompute ----
    const int lrow = lid & 15;
    const uint32_t lcol = (uint32_t)(lid >> 4);
    uint32_t aOff[2], aXr[2], bOff[4], bXr[4];
#pragma unroll
    for (int mt = 0; mt < 2; mt++) {
        int r = wm * 32 + mt * 16 + lrow;
        aOff[mt] = (uint32_t)(r * 128);
        aXr[mt]  = (uint32_t)(r & 7);
    }
#pragma unroll
    for (int nt2 = 0; nt2 < 4; nt2++) {
        int r = wn * 64 + nt2 * 16 + lrow;
        bOff[nt2] = (uint32_t)(r * 128);
        bXr[nt2]  = (uint32_t)(r & 7);
    }

    float acc[2][8][4];
#pragma unroll
    for (int mt = 0; mt < 2; mt++)
#pragma unroll
        for (int nt = 0; nt < 8; nt++)
#pragma unroll
            for (int j = 0; j < 4; j++) acc[mt][nt][j] = 0.0f;

    // ---- prologue: fill STAGES-1 stages ----
#pragma unroll
    for (int c = 0; c < STAGES - 1; c++) {
        const uint32_t stg = sb + (uint32_t)c * STAGE_BYTES;
        const int k0 = c * KC;
#pragma unroll
        for (int i = 0; i < 2; i++)
            cp16(stg + ST_A + aDst[i], xh + aSrc[i] + k0);
#pragma unroll
        for (int i = 0; i < 4; i++)
            cp16(stg + ST_B + bDst[i], wh + bSrc[i] + k0);
        CP_COMMIT();
    }

    // ---- mainloop ----
    for (int c = 0; c < NCHUNK; c++) {
        CP_WAIT(STAGES - 2);
        __syncthreads();

        // issue loads for chunk c + STAGES-1
        if (c + STAGES - 1 < NCHUNK) {
            const uint32_t stg = sb + (uint32_t)((c + STAGES - 1) & (STAGES - 1)) * STAGE_BYTES;
            const int k0 = (c + STAGES - 1) * KC;
#pragma unroll
            for (int i = 0; i < 2; i++)
                cp16(stg + ST_A + aDst[i], xh + aSrc[i] + k0);
#pragma unroll
            for (int i = 0; i < 4; i++)
                cp16(stg + ST_B + bDst[i], wh + bSrc[i] + k0);
        }
        CP_COMMIT();

        // ---- compute on stage c: 4 k16-steps, light B ping-pong ----
        const uint32_t stA = sb + (uint32_t)(c & (STAGES - 1)) * STAGE_BYTES + ST_A;
        const uint32_t stB = sb + (uint32_t)(c & (STAGES - 1)) * STAGE_BYTES + ST_B;

#pragma unroll
        for (int ks = 0; ks < 4; ks++) {
            const uint32_t kc = (uint32_t)(ks * 2) + lcol;
            uint32_t ah[2][4];
#pragma unroll
            for (int mt = 0; mt < 2; mt++)
                ldmx4(ah[mt], stA + aOff[mt] + ((kc ^ aXr[mt]) << 4));
            uint32_t bh[2][4];
            ldmx4(bh[0], stB + bOff[0] + ((kc ^ bXr[0]) << 4));
#pragma unroll
            for (int nt2 = 0; nt2 < 4; nt2++) {
                const int bcur = nt2 & 1;
                if (nt2 < 3)
                    ldmx4(bh[bcur ^ 1], stB + bOff[nt2 + 1] + ((kc ^ bXr[nt2 + 1]) << 4));
                // 4 MMAs on current fragments
#pragma unroll
                for (int mt = 0; mt < 2; mt++) {
                    mma16816(acc[mt][nt2 * 2],     ah[mt], bh[bcur][0], bh[bcur][2]);
                    mma16816(acc[mt][nt2 * 2 + 1], ah[mt], bh[bcur][1], bh[bcur][3]);
                }
            }
        }
    }

    // ---- epilogue: bias + direct float2 stores ----
    const int gr = lid >> 2;
    const int gc = (lid & 3) * 2;
#pragma unroll
    for (int mt = 0; mt < 2; mt++) {
        const int rbase = m0 + wm * 32 + mt * 16 + gr;
#pragma unroll
        for (int nt = 0; nt < 8; nt++) {
            const int col = n0 + wn * 64 + nt * 8 + gc;
            const float b0 = __ldg(bias + col);
            const float b1 = __ldg(bias + col + 1);
            float2 v0 = make_float2(acc[mt][nt][0] + b0, acc[mt][nt][1] + b1);
            float2 v1 = make_float2(acc[mt][nt][2] + b0, acc[mt][nt][3] + b1);
            *reinterpret_cast<float2*>(out + (size_t)rbase * OUT_DIM + col) = v0;
            *reinterpret_cast<float2*>(out + (size_t)(rbase + 8) * OUT_DIM + col) = v1;
        }
    }
}

// ---------------- launch ----------------
extern "C" void kernel_launch(void* const* d_in, const int* in_sizes, int n_in,
                              void* d_out, int out_size) {
    (void)in_sizes; (void)n_in; (void)out_size;
    const float* x = (const float*)d_in[0];
    const float* W = (const float*)d_in[1];
    const float* b = (const float*)d_in[2];
    float* out = (float*)d_out;

    cvt_kernel<<<4096, 256>>>((const float4*)x, (const float4*)W);

    cudaFuncSetAttribute(gemm_fp16_kernel,
                         cudaFuncAttributeMaxDynamicSharedMemorySize, SMEM_TOTAL);
    dim3 grid(OUT_DIM / NT, BATCH / MT);  // (16, 32)
    gemm_fp16_kernel<<<grid, 512, SMEM_TOTAL>>>(b, out);
}

// round 12
// speedup vs baseline: 3.4466x; 1.1248x over previous
#include <cuda_runtime.h>
#include <cuda_fp16.h>
#include <cstdint>

// ============================================================
// out[4096,4096] = x[4096,4096] @ W^T[4096,4096] + b
// SINGLE fp16 GEMM:  out ≈ fp16(x) @ fp16(W)^T + b  (rel_err ~2.8e-4)
// mma.sync HMMA fp32-acc.
// 2 CTAs/SM x 4 warps, CTA tile 128x128, warp tile 64x64:
//   minimizes SMEM crossbar bytes/FLOP (was co-critical with tensor pipe)
//   while 2 desynced CTAs cover each other's barrier bubbles.
// ============================================================

#define BATCH   4096
#define IN_DIM  4096
#define OUT_DIM 4096

__device__ __half g_xh[(size_t)BATCH * IN_DIM];
__device__ __half g_wh[(size_t)OUT_DIM * IN_DIM];

// ---------------- PTX helpers ----------------
__device__ __forceinline__ uint32_t smem_to_u32(const void* p) {
    uint32_t a;
    asm("{ .reg .u64 t; cvta.to.shared.u64 t, %1; cvt.u32.u64 %0, t; }" : "=r"(a) : "l"(p));
    return a;
}

__device__ __forceinline__ void cp16(uint32_t dst, const void* src) {
    asm volatile("cp.async.cg.shared.global [%0], [%1], 16;"
                 :: "r"(dst), "l"(__cvta_generic_to_global(src)) : "memory");
}

#define CP_COMMIT() asm volatile("cp.async.commit_group;" ::: "memory")
#define CP_WAIT(n)  asm volatile("cp.async.wait_group %0;" :: "n"(n) : "memory")

__device__ __forceinline__ void ldmx4(uint32_t* r, uint32_t addr) {
    asm volatile("ldmatrix.sync.aligned.m8n8.x4.shared.b16 {%0,%1,%2,%3}, [%4];"
                 : "=r"(r[0]), "=r"(r[1]), "=r"(r[2]), "=r"(r[3]) : "r"(addr));
}

__device__ __forceinline__ void mma16816(float* d, const uint32_t* a,
                                         uint32_t b0, uint32_t b1) {
    asm volatile(
        "mma.sync.aligned.m16n8k16.row.col.f32.f16.f16.f32 "
        "{%0,%1,%2,%3}, {%4,%5,%6,%7}, {%8,%9}, {%0,%1,%2,%3};"
        : "+f"(d[0]), "+f"(d[1]), "+f"(d[2]), "+f"(d[3])
        : "r"(a[0]), "r"(a[1]), "r"(a[2]), "r"(a[3]), "r"(b0), "r"(b1));
}

// ---------------- convert: fp32 -> fp16 (x and W in one kernel) ----------------
__global__ __launch_bounds__(256) void cvt_kernel(const float4* __restrict__ x,
                                                  const float4* __restrict__ w) {
    const int n4 = (int)(((size_t)BATCH * IN_DIM) / 4);
    uint2* xh = reinterpret_cast<uint2*>(g_xh);
    uint2* wh = reinterpret_cast<uint2*>(g_wh);
    const int stride = gridDim.x * blockDim.x;
    for (int i = blockIdx.x * blockDim.x + threadIdx.x; i < 2 * n4; i += stride) {
        const bool isW = (i >= n4);
        const int j = isW ? i - n4 : i;
        float4 v = isW ? w[j] : x[j];
        __half2 p0 = make_half2(__float2half_rn(v.x), __float2half_rn(v.y));
        __half2 p1 = make_half2(__float2half_rn(v.z), __float2half_rn(v.w));
        uint2 r = make_uint2(*reinterpret_cast<uint32_t*>(&p0),
                             *reinterpret_cast<uint32_t*>(&p1));
        if (isW) wh[j] = r; else xh[j] = r;
    }
}

// ---------------- GEMM ----------------
// CTA tile 128x128, 128 threads (4 warps, 2x2), warp tile 64x64.
// K-chunk = 64 fp16, 3-stage cp.async pipeline (32 KB/stage, 96 KB/CTA).
static constexpr int MT = 128;
static constexpr int NT = 128;
static constexpr int KC = 64;
static constexpr int STAGES = 3;
static constexpr int NCHUNK = IN_DIM / KC;              // 64
static constexpr uint32_t ST_A = 0;                     // 128 rows x 128B = 16 KB
static constexpr uint32_t ST_B = 16384;                 // 128 rows x 128B = 16 KB
static constexpr uint32_t STAGE_BYTES = 32768;          // 32 KB
static constexpr uint32_t SMEM_TOTAL = STAGES * STAGE_BYTES;  // 96 KB

// SMEM tile: row pitch 128B (64 fp16), SW128-style swizzle: 16B-col ^= row&7
__device__ __forceinline__ uint32_t swz(int row, int c16) {
    return (uint32_t)(row * 128 + ((c16 ^ (row & 7)) << 4));
}

__global__ __launch_bounds__(128, 2) void gemm_fp16_kernel(const float* __restrict__ bias,
                                                           float* __restrict__ out) {
    extern __shared__ char smem[];
    const uint32_t sb = smem_to_u32(smem);
    const int tid = threadIdx.x;
    const int wid = tid >> 5;
    const int lid = tid & 31;
    const int wm = wid >> 1;          // 0..1 : M warp (64 rows)
    const int wn = wid & 1;           // 0..1 : N warp (64 cols)

    // CTA swizzle: width-16 super-columns -> concurrent CTAs stay L2-compact
    const int bid = blockIdx.x;
    const int bx = (bid & 15) | ((bid >> 9) << 4);
    const int by = (bid >> 4) & 31;
    const int m0 = by * MT;
    const int n0 = bx * NT;

    // ---- producer base+stride addressing ----
    // item i (i=0..7): row = (tid>>3) + 16*i, c16 = tid&7
    // (row&7) invariant under +16 -> swizzled dst stride is constant 2048.
    const int prow = tid >> 3, pc16 = tid & 7;
    const __half* srcA = g_xh + (size_t)(m0 + prow) * IN_DIM + pc16 * 8;
    const __half* srcB = g_wh + (size_t)(n0 + prow) * IN_DIM + pc16 * 8;
    const uint32_t pDst = swz(prow, pc16);
    const size_t rowStep = (size_t)16 * IN_DIM;

    // ---- ldmatrix per-thread precompute ----
    const int lrow = lid & 15;
    const uint32_t lcol = (uint32_t)(lid >> 4);
    uint32_t aOff[4], aXr[4], bOff[4], bXr[4];
#pragma unroll
    for (int mt = 0; mt < 4; mt++) {
        int r = wm * 64 + mt * 16 + lrow;
        aOff[mt] = (uint32_t)(r * 128);
        aXr[mt]  = (uint32_t)(r & 7);
    }
#pragma unroll
    for (int nt2 = 0; nt2 < 4; nt2++) {
        int r = wn * 64 + nt2 * 16 + lrow;
        bOff[nt2] = (uint32_t)(r * 128);
        bXr[nt2]  = (uint32_t)(r & 7);
    }

    float acc[4][8][4];
#pragma unroll
    for (int mt = 0; mt < 4; mt++)
#pragma unroll
        for (int nt = 0; nt < 8; nt++)
#pragma unroll
            for (int j = 0; j < 4; j++) acc[mt][nt][j] = 0.0f;

    // ---- prologue: fill STAGES-1 stages ----
#pragma unroll
    for (int c = 0; c < STAGES - 1; c++) {
        const uint32_t stg = sb + (uint32_t)c * STAGE_BYTES;
        const int k0 = c * KC;
#pragma unroll
        for (int i = 0; i < 8; i++) {
            cp16(stg + ST_A + pDst + i * 2048, srcA + k0 + i * rowStep);
            cp16(stg + ST_B + pDst + i * 2048, srcB + k0 + i * rowStep);
        }
        CP_COMMIT();
    }

    // ---- mainloop ----
    int s_cons = 0, s_prod = STAGES - 1;
    for (int c = 0; c < NCHUNK; c++) {
        CP_WAIT(STAGES - 2);
        __syncthreads();

        // issue loads for chunk c + STAGES-1
        if (c + STAGES - 1 < NCHUNK) {
            const uint32_t stg = sb + (uint32_t)s_prod * STAGE_BYTES;
            const int k0 = (c + STAGES - 1) * KC;
#pragma unroll
            for (int i = 0; i < 8; i++) {
                cp16(stg + ST_A + pDst + i * 2048, srcA + k0 + i * rowStep);
                cp16(stg + ST_B + pDst + i * 2048, srcB + k0 + i * rowStep);
            }
        }
        CP_COMMIT();

        // ---- compute on stage s_cons: 4 k16-steps, A dbl-buffer + B ping-pong ----
        const uint32_t stA = sb + (uint32_t)s_cons * STAGE_BYTES + ST_A;
        const uint32_t stB = sb + (uint32_t)s_cons * STAGE_BYTES + ST_B;

        uint32_t ah[2][4][4];
        uint32_t bh[2][4];
#pragma unroll
        for (int mt = 0; mt < 4; mt++)
            ldmx4(ah[0][mt], stA + aOff[mt] + ((lcol ^ aXr[mt]) << 4));
        ldmx4(bh[0], stB + bOff[0] + ((lcol ^ bXr[0]) << 4));

#pragma unroll
        for (int ks = 0; ks < 4; ks++) {
            const uint32_t kc  = (uint32_t)(ks * 2) + lcol;
            const uint32_t kcn = kc + 2;
            const int cur = ks & 1;
#pragma unroll
            for (int nt2 = 0; nt2 < 4; nt2++) {
                const int bcur = nt2 & 1;
                // prefetch next B fragment
                if (nt2 < 3)
                    ldmx4(bh[bcur ^ 1], stB + bOff[nt2 + 1] + ((kc ^ bXr[nt2 + 1]) << 4));
                else if (ks < 3)
                    ldmx4(bh[bcur ^ 1], stB + bOff[0] + ((kcn ^ bXr[0]) << 4));
                // prefetch next ks's A fragments mid-stream
                if (nt2 == 1 && ks < 3) {
#pragma unroll
                    for (int mt = 0; mt < 4; mt++)
                        ldmx4(ah[cur ^ 1][mt], stA + aOff[mt] + ((kcn ^ aXr[mt]) << 4));
                }
                // 8 MMAs on current fragments
#pragma unroll
                for (int mt = 0; mt < 4; mt++) {
                    mma16816(acc[mt][nt2 * 2],     ah[cur][mt], bh[bcur][0], bh[bcur][2]);
                    mma16816(acc[mt][nt2 * 2 + 1], ah[cur][mt], bh[bcur][1], bh[bcur][3]);
                }
            }
        }
        if (++s_cons == STAGES) s_cons = 0;
        if (++s_prod == STAGES) s_prod = 0;
    }

    // ---- epilogue: bias + direct float2 stores ----
    const int gr = lid >> 2;
    const int gc = (lid & 3) * 2;
#pragma unroll
    for (int mt = 0; mt < 4; mt++) {
        const int rbase = m0 + wm * 64 + mt * 16 + gr;
#pragma unroll
        for (int nt = 0; nt < 8; nt++) {
            const int col = n0 + wn * 64 + nt * 8 + gc;
            const float b0 = __ldg(bias + col);
            const float b1 = __ldg(bias + col + 1);
            float2 v0 = make_float2(acc[mt][nt][0] + b0, acc[mt][nt][1] + b1);
            float2 v1 = make_float2(acc[mt][nt][2] + b0, acc[mt][nt][3] + b1);
            *reinterpret_cast<float2*>(out + (size_t)rbase * OUT_DIM + col) = v0;
            *reinterpret_cast<float2*>(out + (size_t)(rbase + 8) * OUT_DIM + col) = v1;
        }
    }
}

// ---------------- launch ----------------
extern "C" void kernel_launch(void* const* d_in, const int* in_sizes, int n_in,
                              void* d_out, int out_size) {
    (void)in_sizes; (void)n_in; (void)out_size;
    const float* x = (const float*)d_in[0];
    const float* W = (const float*)d_in[1];
    const float* b = (const float*)d_in[2];
    float* out = (float*)d_out;

    cvt_kernel<<<4096, 256>>>((const float4*)x, (const float4*)W);

    cudaFuncSetAttribute(gemm_fp16_kernel,
                         cudaFuncAttributeMaxDynamicSharedMemorySize, SMEM_TOTAL);
    const int nblocks = (BATCH / MT) * (OUT_DIM / NT);  // 1024
    gemm_fp16_kernel<<<nblocks, 128, SMEM_TOTAL>>>(b, out);
}